// round 11
// baseline (speedup 1.0000x reference)
#include <cuda_runtime.h>
#include <cuda_fp16.h>
#include <cuda_bf16.h>
#include <math.h>

#define NMAX 50000
#define DIM 128
#define KNBR 16
#define HSW 68   // smem row stride in 32-bit words (64 data + 4 pad; 68%32==4)

// Scratch (static device globals — no allocation allowed)
__device__ __half g_E [(size_t)NMAX * DIM];
__device__ __half g_H1[(size_t)NMAX * DIM];
__device__ __half g_C [(size_t)NMAX * 2 * DIM];
__device__ __half g_Wh[256 * 128];   // Wcat^T as [n][k] fp16, row-major

// ---------------------------------------------------------------------------
// fp32 -> fp16 elementwise convert (vectorized); also zeroes the output scalar
// ---------------------------------------------------------------------------
__global__ void f2h_kernel(const float* __restrict__ in, __half* __restrict__ out,
                           int n4, float* __restrict__ loss_out, int loss_n) {
    int i = blockIdx.x * blockDim.x + threadIdx.x;
    if (blockIdx.x == 0 && threadIdx.x < (unsigned)loss_n) loss_out[threadIdx.x] = 0.f;
    if (i < n4) {
        float4 v = __ldg((const float4*)in + i);
        __half2 lo = __floats2half2_rn(v.x, v.y);
        __half2 hi = __floats2half2_rn(v.z, v.w);
        uint2 u;
        u.x = *(unsigned*)&lo;
        u.y = *(unsigned*)&hi;
        ((uint2*)out)[i] = u;
    }
}

// ---------------------------------------------------------------------------
// W prep: g_Wh[n][k] = Wcat[k][n] = (n<128) ? W1[k][n] : W1[k+128][n-128]
// ---------------------------------------------------------------------------
__global__ void w_prep_kernel(const float* __restrict__ W1, __half* __restrict__ Wh) {
    int idx = blockIdx.x * blockDim.x + threadIdx.x;   // over 256*128 = 32768
    if (idx < 256 * 128) {
        int r = idx >> 7;
        int c = idx & 127;
        float v = W1[idx];
        int k = r & 127;
        int n = c + ((r >> 7) << 7);
        Wh[n * 128 + k] = __float2half_rn(v);
    }
}

// ---------------------------------------------------------------------------
// Mean neighbor aggregation (layer 1), fp16: warp = 2 nodes, HADD2 accumulate.
// ---------------------------------------------------------------------------
__global__ void agg_kernel(const __half* __restrict__ in,
                           const int* __restrict__ nbr,
                           __half* __restrict__ out, int N) {
    int gw = (blockIdx.x * blockDim.x + threadIdx.x) >> 5;
    int lane = threadIdx.x & 31;
    int node = gw * 2 + (lane >> 4);
    if (node >= N) return;
    int sl = lane & 15;
    const int* nb = nbr + (size_t)node * KNBR;
    const uint4* in16 = (const uint4*)in;
    __half2 z = __float2half2_rn(0.f);
    __half2 a0 = z, a1 = z, a2 = z, a3 = z;
#pragma unroll
    for (int k = 0; k < KNBR; k++) {
        int idx = __ldg(nb + k);
        uint4 v = __ldg(in16 + (size_t)idx * 16 + sl);
        a0 = __hadd2(a0, *(__half2*)&v.x);
        a1 = __hadd2(a1, *(__half2*)&v.y);
        a2 = __hadd2(a2, *(__half2*)&v.z);
        a3 = __hadd2(a3, *(__half2*)&v.w);
    }
    __half2 s = __float2half2_rn(1.0f / (float)KNBR);
    a0 = __hmul2(a0, s); a1 = __hmul2(a1, s);
    a2 = __hmul2(a2, s); a3 = __hmul2(a3, s);
    uint4 r;
    r.x = *(unsigned*)&a0; r.y = *(unsigned*)&a1;
    r.z = *(unsigned*)&a2; r.w = *(unsigned*)&a3;
    ((uint4*)out)[(size_t)node * 16 + sl] = r;
}

// ---------------------------------------------------------------------------
// fp16 MMA + ldmatrix helpers
// ---------------------------------------------------------------------------
__device__ __forceinline__ void mma_f16(float* d, const unsigned* a, const unsigned* b) {
    asm("mma.sync.aligned.m16n8k16.row.col.f32.f16.f16.f32 "
        "{%0,%1,%2,%3}, {%4,%5,%6,%7}, {%8,%9}, {%0,%1,%2,%3};"
        : "+f"(d[0]), "+f"(d[1]), "+f"(d[2]), "+f"(d[3])
        : "r"(a[0]), "r"(a[1]), "r"(a[2]), "r"(a[3]), "r"(b[0]), "r"(b[1]));
}

__device__ __forceinline__ void ldsm_x4(unsigned* r, unsigned addr) {
    asm volatile("ldmatrix.sync.aligned.m8n8.x4.shared.b16 {%0,%1,%2,%3}, [%4];"
                 : "=r"(r[0]), "=r"(r[1]), "=r"(r[2]), "=r"(r[3]) : "r"(addr));
}

// ---------------------------------------------------------------------------
// FUSED agg-layer-2 + projection GEMM (R9 structure — best known).
// Per 64-row tile: gather H2 rows from H1 (mean of 16 nbrs) into smem,
// then C[tile,256] = H2_tile @ Wcat via mma.sync.
// Ws full [256n][136 halves] = 69.6KB; Hs double-buffered 2x[64][136] = 34.8KB
//   -> 104.4KB/CTA -> 2 CTAs/SM.
// ---------------------------------------------------------------------------
extern __shared__ unsigned s_dyn_u[];

__global__ __launch_bounds__(256, 2) void agg_gemm_kernel(const __half* __restrict__ H1,
                                                          const int* __restrict__ nbr,
                                                          const __half* __restrict__ Wh,
                                                          __half* __restrict__ C, int N) {
    unsigned* Ws  = s_dyn_u;                 // words; halves [256][136]
    unsigned* Hs0 = s_dyn_u + 256 * HSW;     // words; halves [64][136]
    unsigned* Hs1 = Hs0 + 64 * HSW;
    int t = threadIdx.x;
    int lane = t & 31;
    int warp = t >> 5;
    int mwarp = warp >> 2;      // 0..1
    int nwarp = warp & 3;       // 0..3
    int g  = lane >> 2;
    int tg = lane & 3;
    int n0 = nwarp * 64;

    // Fill Ws (all 256 cols) from pre-converted fp16 Wh[n][k] (vectorized)
    {
        const uint4* W16 = (const uint4*)Wh;
#pragma unroll
        for (int j = 0; j < 16; j++) {
            int i = t + j * 256;
            int n = i >> 4;
            int q = i & 15;
            uint4 v = __ldg(W16 + i);
            *(uint4*)(Ws + n * HSW + q * 4) = v;
        }
    }

    unsigned hs0_b = (unsigned)__cvta_generic_to_shared(Hs0);
    unsigned hs1_b = (unsigned)__cvta_generic_to_shared(Hs1);
    unsigned ws_base = (unsigned)__cvta_generic_to_shared(Ws);
    unsigned a_row  = lane & 15;
    unsigned a_koff = (lane >> 4) * 8;
    unsigned b_n    = (lane & 7) + ((lane >> 4) << 3);
    unsigned b_koff = ((lane >> 3) & 1) << 3;

    int numRowTiles = (N + 63) >> 6;
    int stride = gridDim.x;
    int rt0 = blockIdx.x;

    int agg_sub  = lane >> 4;
    int agg_sl   = lane & 15;
    const uint4* H1_16 = (const uint4*)H1;
    const __half2 hscale = __float2half2_rn(1.0f / (float)KNBR);

    // Prologue: aggregate first tile into Hs0
    if (rt0 < numRowTiles) {
        int row0 = rt0 * 64;
#pragma unroll
        for (int round = 0; round < 4; round++) {
            int r_local = round * 16 + warp * 2 + agg_sub;
            int node = row0 + r_local;
            __half2 z = __float2half2_rn(0.f);
            __half2 a0 = z, a1 = z, a2 = z, a3 = z;
            if (node < N) {
                const int* nb = nbr + (size_t)node * KNBR;
#pragma unroll
                for (int k = 0; k < KNBR; k++) {
                    int idx = __ldg(nb + k);
                    uint4 v = __ldg(H1_16 + (size_t)idx * 16 + agg_sl);
                    a0 = __hadd2(a0, *(__half2*)&v.x);
                    a1 = __hadd2(a1, *(__half2*)&v.y);
                    a2 = __hadd2(a2, *(__half2*)&v.z);
                    a3 = __hadd2(a3, *(__half2*)&v.w);
                }
                a0 = __hmul2(a0, hscale); a1 = __hmul2(a1, hscale);
                a2 = __hmul2(a2, hscale); a3 = __hmul2(a3, hscale);
            }
            uint4 r;
            r.x = *(unsigned*)&a0; r.y = *(unsigned*)&a1;
            r.z = *(unsigned*)&a2; r.w = *(unsigned*)&a3;
            *(uint4*)(Hs0 + r_local * HSW + agg_sl * 4) = r;
        }
    }

    int cur = 0;
    for (int rt = rt0; rt < numRowTiles; rt += stride) {
        int row0 = rt * 64;
        __syncthreads();

        unsigned hs_base = cur ? hs1_b : hs0_b;

        float acc[2][8][4];
#pragma unroll
        for (int mf = 0; mf < 2; mf++)
#pragma unroll
            for (int nf = 0; nf < 8; nf++)
#pragma unroll
                for (int e = 0; e < 4; e++) acc[mf][nf][e] = 0.f;

#pragma unroll
        for (int kk = 0; kk < 8; kk++) {
            unsigned k0 = kk * 16;
            unsigned a[2][4];
#pragma unroll
            for (int mf = 0; mf < 2; mf++) {
                unsigned addr = hs_base +
                    ((mwarp * 32 + mf * 16 + a_row) * (2 * HSW) + k0 + a_koff) * 2;
                ldsm_x4(a[mf], addr);
            }
            unsigned b[8][2];
#pragma unroll
            for (int j = 0; j < 4; j++) {
                unsigned addr = ws_base +
                    ((n0 + j * 16 + b_n) * (2 * HSW) + k0 + b_koff) * 2;
                unsigned r[4];
                ldsm_x4(r, addr);
                b[2 * j][0] = r[0]; b[2 * j][1] = r[1];
                b[2 * j + 1][0] = r[2]; b[2 * j + 1][1] = r[3];
            }
#pragma unroll
            for (int mf = 0; mf < 2; mf++)
#pragma unroll
                for (int nf = 0; nf < 8; nf++)
                    mma_f16(acc[mf][nf], a[mf], b[nf]);
        }

        // Aggregate NEXT tile into Hs[nxt]
        int rtn = rt + stride;
        if (rtn < numRowTiles) {
            unsigned* Hn = cur ? Hs0 : Hs1;
            int rown0 = rtn * 64;
#pragma unroll
            for (int round = 0; round < 4; round++) {
                int r_local = round * 16 + warp * 2 + agg_sub;
                int node = rown0 + r_local;
                __half2 z = __float2half2_rn(0.f);
                __half2 a0 = z, a1 = z, a2 = z, a3 = z;
                if (node < N) {
                    const int* nb = nbr + (size_t)node * KNBR;
#pragma unroll
                    for (int k = 0; k < KNBR; k++) {
                        int idx = __ldg(nb + k);
                        uint4 v = __ldg(H1_16 + (size_t)idx * 16 + agg_sl);
                        a0 = __hadd2(a0, *(__half2*)&v.x);
                        a1 = __hadd2(a1, *(__half2*)&v.y);
                        a2 = __hadd2(a2, *(__half2*)&v.z);
                        a3 = __hadd2(a3, *(__half2*)&v.w);
                    }
                    a0 = __hmul2(a0, hscale); a1 = __hmul2(a1, hscale);
                    a2 = __hmul2(a2, hscale); a3 = __hmul2(a3, hscale);
                }
                uint4 r;
                r.x = *(unsigned*)&a0; r.y = *(unsigned*)&a1;
                r.z = *(unsigned*)&a2; r.w = *(unsigned*)&a3;
                *(uint4*)(Hn + r_local * HSW + agg_sl * 4) = r;
            }
        }

        // Epilogue -> fp16 C
        unsigned* C32 = (unsigned*)C;
#pragma unroll
        for (int mf = 0; mf < 2; mf++) {
            int r_lo = row0 + mwarp * 32 + mf * 16 + g;
            int r_hi = r_lo + 8;
#pragma unroll
            for (int nf = 0; nf < 8; nf++) {
                int colh = (n0 + nf * 8 + tg * 2) >> 1;
                if (r_lo < N) {
                    __half2 h = __floats2half2_rn(acc[mf][nf][0], acc[mf][nf][1]);
                    C32[(size_t)r_lo * 128 + colh] = *(unsigned*)&h;
                }
                if (r_hi < N) {
                    __half2 h = __floats2half2_rn(acc[mf][nf][2], acc[mf][nf][3]);
                    C32[(size_t)r_hi * 128 + colh] = *(unsigned*)&h;
                }
            }
        }
        cur ^= 1;
    }
}

// ---------------------------------------------------------------------------
// Per-pair loss: one warp handles FOUR pairs (8 lanes each, 16 features/lane).
// Per lane: 4 independent LDG.128 (MLP=4); 3-level butterfly reduction.
// ---------------------------------------------------------------------------
__global__ void pair_kernel(const int* __restrict__ pairs,
                            const int* __restrict__ labels,
                            const __half* __restrict__ C,
                            const float* __restrict__ b1,
                            const float* __restrict__ W2,
                            const float* __restrict__ b2,
                            float* __restrict__ out, int B) {
    int lane = threadIdx.x & 31;
    int sl = lane & 7;            // feature lane: features 16sl .. 16sl+15
    int wib = threadIdx.x >> 5;
    int warpsPerBlock = blockDim.x >> 5;
    int gwarp = blockIdx.x * warpsPerBlock + wib;
    int nwarps = gridDim.x * warpsPerBlock;
    int side = lane >> 3;         // 0..3: which pair within the warp

    // Per-lane constants for features 16sl..16sl+15
    float bias[16];
#pragma unroll
    for (int q = 0; q < 4; q++) {
        float4 bv = __ldg((const float4*)b1 + 4 * sl + q);
        bias[4 * q + 0] = bv.x; bias[4 * q + 1] = bv.y;
        bias[4 * q + 2] = bv.z; bias[4 * q + 3] = bv.w;
    }
    float w20[16], w21[16];
#pragma unroll
    for (int q = 0; q < 16; q++) {
        float2 wv = __ldg((const float2*)W2 + 16 * sl + q);
        w20[q] = wv.x; w21[q] = wv.y;
    }
    float b2_0 = __ldg(b2 + 0), b2_1 = __ldg(b2 + 1);

    const uint4* C16 = (const uint4*)C;   // 32 uint4 per 256-half row
    float lsum = 0.f;

    for (int p = gwarp * 4 + side; p < B; p += nwarps * 4) {
        int src = __ldg(pairs + 2 * p);
        int dst = __ldg(pairs + 2 * p + 1);
        // src cols 16sl..16sl+15 ; dst cols 128+16sl..128+16sl+15
        uint4 ua0 = __ldg(C16 + (size_t)src * 32 + 2 * sl);
        uint4 ua1 = __ldg(C16 + (size_t)src * 32 + 2 * sl + 1);
        uint4 ub0 = __ldg(C16 + (size_t)dst * 32 + 16 + 2 * sl);
        uint4 ub1 = __ldg(C16 + (size_t)dst * 32 + 16 + 2 * sl + 1);
        float l0 = 0.f, l1 = 0.f;
        const unsigned* au0 = (const unsigned*)&ua0;
        const unsigned* au1 = (const unsigned*)&ua1;
        const unsigned* bu0 = (const unsigned*)&ub0;
        const unsigned* bu1 = (const unsigned*)&ub1;
#pragma unroll
        for (int c = 0; c < 4; c++) {
            float2 af = __half22float2(*(__half2*)&au0[c]);
            float2 bf = __half22float2(*(__half2*)&bu0[c]);
            float h0 = fmaxf(af.x + bf.x + bias[2 * c], 0.f);
            float h1 = fmaxf(af.y + bf.y + bias[2 * c + 1], 0.f);
            l0 += h0 * w20[2 * c] + h1 * w20[2 * c + 1];
            l1 += h0 * w21[2 * c] + h1 * w21[2 * c + 1];
            float2 af2 = __half22float2(*(__half2*)&au1[c]);
            float2 bf2 = __half22float2(*(__half2*)&bu1[c]);
            float h2 = fmaxf(af2.x + bf2.x + bias[8 + 2 * c], 0.f);
            float h3 = fmaxf(af2.y + bf2.y + bias[8 + 2 * c + 1], 0.f);
            l0 += h2 * w20[8 + 2 * c] + h3 * w20[8 + 2 * c + 1];
            l1 += h2 * w21[8 + 2 * c] + h3 * w21[8 + 2 * c + 1];
        }
        // 8-lane butterfly reduction (stays within each 8-lane group)
#pragma unroll
        for (int off = 1; off < 8; off <<= 1) {
            l0 += __shfl_xor_sync(0xFFFFFFFFu, l0, off);
            l1 += __shfl_xor_sync(0xFFFFFFFFu, l1, off);
        }
        if (sl == 0) {
            l0 += b2_0; l1 += b2_1;
            float m = fmaxf(l0, l1);
            float e0 = __expf(l0 - m), e1 = __expf(l1 - m);
            float inv = 1.f / (e0 + e1);
            float p0 = e0 * inv, p1 = e1 * inv;
            float mm = fmaxf(p0, p1);
            float lse = mm + __logf(__expf(p0 - mm) + __expf(p1 - mm));
            int lab = __ldg(labels + p);
            float pl = lab ? p1 : p0;
            lsum += (lse - pl);
        }
    }

    // lsum lives on lanes 0, 8, 16, 24 — combine, then block-reduce
    lsum += __shfl_down_sync(0xFFFFFFFFu, lsum, 8);
    lsum += __shfl_down_sync(0xFFFFFFFFu, lsum, 16);
    __shared__ float ssum[32];
    if (lane == 0) ssum[wib] = lsum;
    __syncthreads();
    if (threadIdx.x == 0) {
        float s = 0.f;
        for (int w = 0; w < warpsPerBlock; w++) s += ssum[w];
        atomicAdd(out, s / (float)B);
    }
}

// ---------------------------------------------------------------------------
extern "C" void kernel_launch(void* const* d_in, const int* in_sizes, int n_in,
                              void* d_out, int out_size) {
    const int*   pairs     = (const int*)d_in[0];
    const int*   labels    = (const int*)d_in[1];
    const int*   neighbors = (const int*)d_in[2];
    const float* embedding = (const float*)d_in[3];
    const float* W1        = (const float*)d_in[4];
    const float* b1        = (const float*)d_in[5];
    const float* W2        = (const float*)d_in[6];
    const float* b2        = (const float*)d_in[7];

    int B = in_sizes[0] / 2;
    int N = in_sizes[2] / KNBR;

    __half *E, *H1, *C, *Wh;
    cudaGetSymbolAddress((void**)&E,  g_E);
    cudaGetSymbolAddress((void**)&H1, g_H1);
    cudaGetSymbolAddress((void**)&C,  g_C);
    cudaGetSymbolAddress((void**)&Wh, g_Wh);

    float* out = (float*)d_out;

    // Convert embedding to fp16 (also zeroes the loss accumulator)
    int n4 = N * DIM / 4;
    f2h_kernel<<<(n4 + 255) / 256, 256>>>(embedding, E, n4, out, out_size);

    // Prepare Wcat^T fp16
    w_prep_kernel<<<128, 256>>>(W1, Wh);

    // Aggregation layer 1
    int aggBlocks = (N / 2 + 7) / 8;
    agg_kernel<<<aggBlocks, 256>>>(E, neighbors, H1, N);

    // Fused agg layer 2 + projection GEMM (2 CTAs/SM)
    size_t smem = (size_t)(256 * HSW + 2 * 64 * HSW) * sizeof(unsigned);  // 104448 B
    cudaFuncSetAttribute(agg_gemm_kernel, cudaFuncAttributeMaxDynamicSharedMemorySize, (int)smem);
    agg_gemm_kernel<<<296, 256, smem>>>(H1, neighbors, Wh, C, N);

    // Pair loss (4 pairs per warp, fp16 C gathers)
    pair_kernel<<<1184, 256>>>(pairs, labels, C, b1, W2, b2, out, B);
}